// round 2
// baseline (speedup 1.0000x reference)
#include <cuda_runtime.h>
#include <math.h>

#define D 128
#define NDST 100000
#define NSRC0 400000
#define NSRC1 10000
#define K0 8
#define K1 4
#define SPB ((NDST + 127) / 128)

// ---------------- scratch (static device globals; no allocation) ----------------
__device__ float g_feat0[(size_t)NSRC0 * D];   // 204.8 MB
__device__ float g_feat1[(size_t)NSRC1 * D];   // 5.1 MB
__device__ float g_el0[NSRC0];
__device__ float g_el1[NSRC1];
__device__ float g_er0[NDST];
__device__ float g_er1[NDST];
__device__ float g_e0[(size_t)NDST * D];       // 51.2 MB
__device__ float g_e1[(size_t)NDST * D];       // 51.2 MB
__device__ float g_w0[D];                      // W_dst0 @ a_r0
__device__ float g_w1[D];                      // W_dst1 @ a_r1
__device__ float g_wt[D * D];                  // W_fc transposed
__device__ float g_sp0p[SPB * D];              // per-block partials (deterministic)
__device__ float g_sp1p[SPB * D];
__device__ float g_beta[2];

// ---------------- prep: er-vectors, W_fc transpose ----------------
__global__ void prep_kernel(const float* __restrict__ Wd0, const float* __restrict__ ar0,
                            const float* __restrict__ Wd1, const float* __restrict__ ar1,
                            const float* __restrict__ Wfc) {
    int t = threadIdx.x;  // 128 threads
    float s0 = 0.f, s1 = 0.f;
    for (int d = 0; d < D; d++) {
        s0 = fmaf(Wd0[t * D + d], ar0[d], s0);
        s1 = fmaf(Wd1[t * D + d], ar1[d], s1);
    }
    g_w0[t] = s0;
    g_w1[t] = s1;
    for (int d = 0; d < D; d++) g_wt[d * D + t] = Wfc[t * D + d];
}

// ---------------- feat GEMM: C = A[N,128] @ W[128,128], el = C @ a_l ----------------
// 128x128 tile per block, 256 threads, 8x8 register tile per thread, BK=32.
template <int REL>
__global__ __launch_bounds__(256) void gemm_feat(const float* __restrict__ A,
                                                 const float* __restrict__ W,
                                                 const float* __restrict__ al, int N) {
    float* __restrict__ C  = REL ? g_feat1 : g_feat0;
    float* __restrict__ el = REL ? g_el1 : g_el0;
    __shared__ float As[128 * 32];
    __shared__ float Ws[32 * 128];

    const int tid = threadIdx.x;
    const int tx = tid & 15;     // 16 col-groups of 8 cols
    const int ty = tid >> 4;     // 16 row-groups of 8 rows
    const int c0 = tx * 8;
    const int r0 = ty * 8;
    const int rowBase = blockIdx.x * 128;

    float acc[8][8];
#pragma unroll
    for (int i = 0; i < 8; i++)
#pragma unroll
        for (int j = 0; j < 8; j++) acc[i][j] = 0.f;

    for (int kb = 0; kb < D; kb += 32) {
#pragma unroll
        for (int p = 0; p < 4; p++) {
            int lin = tid + p * 256;
            int r = lin >> 3, q = lin & 7;
            int grow = rowBase + r;
            float4 v = make_float4(0.f, 0.f, 0.f, 0.f);
            if (grow < N) v = *(const float4*)(A + (size_t)grow * D + kb + q * 4);
            *(float4*)(As + r * 32 + q * 4) = v;
        }
#pragma unroll
        for (int p = 0; p < 4; p++) {
            int lin = tid + p * 256;
            int kr = lin >> 5, q = lin & 31;
            *(float4*)(Ws + kr * 128 + q * 4) =
                *(const float4*)(W + (size_t)(kb + kr) * D + q * 4);
        }
        __syncthreads();
#pragma unroll 8
        for (int k = 0; k < 32; k++) {
            float a[8];
#pragma unroll
            for (int i = 0; i < 8; i++) a[i] = As[(r0 + i) * 32 + k];  // warp broadcast
            float4 bv0 = *(float4*)(Ws + k * 128 + c0);
            float4 bv1 = *(float4*)(Ws + k * 128 + c0 + 4);
            float b[8] = {bv0.x, bv0.y, bv0.z, bv0.w, bv1.x, bv1.y, bv1.z, bv1.w};
#pragma unroll
            for (int i = 0; i < 8; i++)
#pragma unroll
                for (int j = 0; j < 8; j++) acc[i][j] = fmaf(a[i], b[j], acc[i][j]);
        }
        __syncthreads();
    }

    // epilogue: store feat + fused el = feat @ a_l (16-lane shuffle reduce)
    float4 av0 = *(const float4*)(al + c0);
    float4 av1 = *(const float4*)(al + c0 + 4);
    float alv[8] = {av0.x, av0.y, av0.z, av0.w, av1.x, av1.y, av1.z, av1.w};
#pragma unroll
    for (int i = 0; i < 8; i++) {
        int grow = rowBase + r0 + i;
        if (grow < N) {
            *(float4*)(C + (size_t)grow * D + c0) =
                make_float4(acc[i][0], acc[i][1], acc[i][2], acc[i][3]);
            *(float4*)(C + (size_t)grow * D + c0 + 4) =
                make_float4(acc[i][4], acc[i][5], acc[i][6], acc[i][7]);
        }
        float p = 0.f;
#pragma unroll
        for (int j = 0; j < 8; j++) p = fmaf(acc[i][j], alv[j], p);
#pragma unroll
        for (int s = 8; s > 0; s >>= 1) p += __shfl_xor_sync(0xffffffffu, p, s, 16);
        if (tx == 0 && grow < N) el[grow] = p;
    }
}

// ---------------- er matvec: er{0,1}[n] = h_dst[n] . w{0,1} ----------------
__global__ void er_kernel(const float* __restrict__ hdst) {
    int gw = (int)(((size_t)blockIdx.x * blockDim.x + threadIdx.x) >> 5);
    int lane = threadIdx.x & 31;
    if (gw >= NDST) return;
    float4 h = *(const float4*)(hdst + (size_t)gw * D + lane * 4);
    float4 a = *(const float4*)(g_w0 + lane * 4);
    float4 b = *(const float4*)(g_w1 + lane * 4);
    float s0 = h.x * a.x + h.y * a.y + h.z * a.z + h.w * a.w;
    float s1 = h.x * b.x + h.y * b.y + h.z * b.z + h.w * b.w;
#pragma unroll
    for (int s = 16; s > 0; s >>= 1) {
        s0 += __shfl_xor_sync(0xffffffffu, s0, s);
        s1 += __shfl_xor_sync(0xffffffffu, s1, s);
    }
    if (lane == 0) {
        g_er0[gw] = s0;
        g_er1[gw] = s1;
    }
}

// ---------------- GAT aggregation: edge softmax + weighted gather ----------------
template <int REL>
__global__ void gat_agg(const int* __restrict__ idx, const float* __restrict__ bias) {
    constexpr int K = REL ? K1 : K0;
    const float* __restrict__ feat = REL ? g_feat1 : g_feat0;
    const float* __restrict__ el = REL ? g_el1 : g_el0;
    const float* __restrict__ er = REL ? g_er1 : g_er0;
    float* __restrict__ eout = REL ? g_e1 : g_e0;

    int n = blockIdx.x;
    __shared__ float e_s[K];
    __shared__ float alpha_s[K];
    __shared__ int idx_s[K];
    int t = threadIdx.x;  // 128

    if (t < K) {
        int i = idx[(size_t)n * K + t];
        float v = el[i] + er[n];
        e_s[t] = v > 0.f ? v : 0.2f * v;  // leaky_relu 0.2
        idx_s[t] = i;
    }
    __syncthreads();
    if (t == 0) {
        float m = e_s[0];
#pragma unroll
        for (int k = 1; k < K; k++) m = fmaxf(m, e_s[k]);
        float sum = 0.f;
        float p[K];
#pragma unroll
        for (int k = 0; k < K; k++) { p[k] = expf(e_s[k] - m); sum += p[k]; }
        float inv = 1.f / sum;
#pragma unroll
        for (int k = 0; k < K; k++) alpha_s[k] = p[k] * inv;
    }
    __syncthreads();
    float acc = bias[t];
#pragma unroll
    for (int k = 0; k < K; k++)
        acc = fmaf(alpha_s[k], feat[(size_t)idx_s[k] * D + t], acc);
    eout[(size_t)n * D + t] = acc;
}

// ---------------- sp reduce: partials of sum_n tanh(e_n @ W_fc^T + b_fc) ----------------
template <int REL>
__global__ __launch_bounds__(256) void sp_gemm(const float* __restrict__ bfc) {
    const float* __restrict__ E = REL ? g_e1 : g_e0;
    float* __restrict__ part = REL ? g_sp1p : g_sp0p;
    const int N = NDST;
    __shared__ float As[128 * 32];
    __shared__ float Ws[32 * 128];
    __shared__ float red[16 * 128];

    const int tid = threadIdx.x;
    const int tx = tid & 15;
    const int ty = tid >> 4;
    const int c0 = tx * 8;
    const int r0 = ty * 8;
    const int rowBase = blockIdx.x * 128;

    float acc[8][8];
#pragma unroll
    for (int i = 0; i < 8; i++)
#pragma unroll
        for (int j = 0; j < 8; j++) acc[i][j] = 0.f;

    for (int kb = 0; kb < D; kb += 32) {
#pragma unroll
        for (int p = 0; p < 4; p++) {
            int lin = tid + p * 256;
            int r = lin >> 3, q = lin & 7;
            int grow = rowBase + r;
            float4 v = make_float4(0.f, 0.f, 0.f, 0.f);
            if (grow < N) v = *(const float4*)(E + (size_t)grow * D + kb + q * 4);
            *(float4*)(As + r * 32 + q * 4) = v;
        }
#pragma unroll
        for (int p = 0; p < 4; p++) {
            int lin = tid + p * 256;
            int kr = lin >> 5, q = lin & 31;
            *(float4*)(Ws + kr * 128 + q * 4) =
                *(const float4*)(g_wt + (size_t)(kb + kr) * D + q * 4);
        }
        __syncthreads();
#pragma unroll 8
        for (int k = 0; k < 32; k++) {
            float a[8];
#pragma unroll
            for (int i = 0; i < 8; i++) a[i] = As[(r0 + i) * 32 + k];
            float4 bv0 = *(float4*)(Ws + k * 128 + c0);
            float4 bv1 = *(float4*)(Ws + k * 128 + c0 + 4);
            float b[8] = {bv0.x, bv0.y, bv0.z, bv0.w, bv1.x, bv1.y, bv1.z, bv1.w};
#pragma unroll
            for (int i = 0; i < 8; i++)
#pragma unroll
                for (int j = 0; j < 8; j++) acc[i][j] = fmaf(a[i], b[j], acc[i][j]);
        }
        __syncthreads();
    }

    float4 b0v = *(const float4*)(bfc + c0);
    float4 b1v = *(const float4*)(bfc + c0 + 4);
    float bf[8] = {b0v.x, b0v.y, b0v.z, b0v.w, b1v.x, b1v.y, b1v.z, b1v.w};
    float s[8] = {0.f, 0.f, 0.f, 0.f, 0.f, 0.f, 0.f, 0.f};
#pragma unroll
    for (int i = 0; i < 8; i++) {
        int grow = rowBase + r0 + i;
        if (grow < N) {
#pragma unroll
            for (int j = 0; j < 8; j++) s[j] += tanhf(acc[i][j] + bf[j]);
        }
    }
#pragma unroll
    for (int j = 0; j < 8; j++) red[ty * 128 + c0 + j] = s[j];
    __syncthreads();
    if (tid < 128) {
        float t = 0.f;
#pragma unroll
        for (int y = 0; y < 16; y++) t += red[y * 128 + tid];
        part[blockIdx.x * 128 + tid] = t;  // deterministic: no atomics
    }
}

// ---------------- beta: softmax over relation scores ----------------
__global__ void beta_kernel(const float* __restrict__ att) {
    __shared__ float r[128];
    __shared__ float res0;
    int t = threadIdx.x;  // 128
    float s0 = 0.f, s1 = 0.f;
    for (int b = 0; b < SPB; b++) {
        s0 += g_sp0p[b * 128 + t];
        s1 += g_sp1p[b * 128 + t];
    }
    float a = att[t];
    r[t] = a * s0;
    __syncthreads();
    for (int off = 64; off > 0; off >>= 1) {
        if (t < off) r[t] += r[t + off];
        __syncthreads();
    }
    if (t == 0) res0 = r[0];
    __syncthreads();
    r[t] = a * s1;
    __syncthreads();
    for (int off = 64; off > 0; off >>= 1) {
        if (t < off) r[t] += r[t + off];
        __syncthreads();
    }
    if (t == 0) {
        float p0 = res0 / (float)NDST;
        float p1 = r[0] / (float)NDST;
        float m = fmaxf(p0, p1);
        float e0 = expf(p0 - m), e1 = expf(p1 - m);
        float inv = 1.f / (e0 + e1);
        g_beta[0] = e0 * inv;
        g_beta[1] = e1 * inv;
    }
}

// ---------------- final blend ----------------
__global__ void combine_kernel(float* __restrict__ out) {
    float b0 = g_beta[0], b1 = g_beta[1];
    size_t i = (size_t)blockIdx.x * blockDim.x + threadIdx.x;
    const size_t tot = (size_t)NDST * D / 4;
    if (i >= tot) return;
    float4 x = ((const float4*)g_e0)[i];
    float4 y = ((const float4*)g_e1)[i];
    float4 r;
    r.x = b0 * x.x + b1 * y.x;
    r.y = b0 * x.y + b1 * y.y;
    r.z = b0 * x.z + b1 * y.z;
    r.w = b0 * x.w + b1 * y.w;
    ((float4*)out)[i] = r;
}

// ---------------- launch ----------------
extern "C" void kernel_launch(void* const* d_in, const int* in_sizes, int n_in,
                              void* d_out, int out_size) {
    const float* h_src0 = (const float*)d_in[0];
    const float* h_src1 = (const float*)d_in[1];
    const float* h_dst  = (const float*)d_in[2];
    const int*   idx0   = (const int*)d_in[3];
    const int*   idx1   = (const int*)d_in[4];
    const float* W_src0 = (const float*)d_in[5];
    const float* W_dst0 = (const float*)d_in[6];
    const float* a_l0   = (const float*)d_in[7];
    const float* a_r0   = (const float*)d_in[8];
    const float* b0     = (const float*)d_in[9];
    const float* W_src1 = (const float*)d_in[10];
    const float* W_dst1 = (const float*)d_in[11];
    const float* a_l1   = (const float*)d_in[12];
    const float* a_r1   = (const float*)d_in[13];
    const float* b1     = (const float*)d_in[14];
    const float* W_fc   = (const float*)d_in[15];
    const float* b_fc   = (const float*)d_in[16];
    const float* att    = (const float*)d_in[17];
    float* out = (float*)d_out;

    prep_kernel<<<1, 128>>>(W_dst0, a_r0, W_dst1, a_r1, W_fc);
    gemm_feat<0><<<NSRC0 / 128, 256>>>(h_src0, W_src0, a_l0, NSRC0);
    gemm_feat<1><<<(NSRC1 + 127) / 128, 256>>>(h_src1, W_src1, a_l1, NSRC1);
    er_kernel<<<(NDST * 32 + 255) / 256, 256>>>(h_dst);
    gat_agg<0><<<NDST, 128>>>(idx0, b0);
    gat_agg<1><<<NDST, 128>>>(idx1, b1);
    sp_gemm<0><<<SPB, 256>>>(b_fc);
    sp_gemm<1><<<SPB, 256>>>(b_fc);
    beta_kernel<<<1, 128>>>(att);
    combine_kernel<<<(NDST * D / 4 + 255) / 256, 256>>>(out);
}

// round 4
// speedup vs baseline: 1.0156x; 1.0156x over previous
#include <cuda_runtime.h>
#include <math.h>

#define D 128
#define NDST 100000
#define NSRC0 400000
#define NSRC1 10000
#define K0 8
#define K1 4
#define SPB ((NDST + 127) / 128)

typedef unsigned long long u64;

// packed f32x2 FMA: d = a*b + d (element-wise on 2 packed floats, rn rounding)
__device__ __forceinline__ void ffma2(u64& d, u64 a, u64 b) {
    asm("fma.rn.f32x2 %0, %1, %2, %0;" : "+l"(d) : "l"(a), "l"(b));
}
__device__ __forceinline__ u64 pack_dup(float a) {
    u64 r;
    asm("mov.b64 %0, {%1, %1};" : "=l"(r) : "f"(a));
    return r;
}
__device__ __forceinline__ void unpack2(u64 p, float& lo, float& hi) {
    asm("mov.b64 {%0, %1}, %2;" : "=f"(lo), "=f"(hi) : "l"(p));
}

// ---------------- scratch (static device globals; no allocation) ----------------
__device__ float g_feat0[(size_t)NSRC0 * D];   // 204.8 MB
__device__ float g_feat1[(size_t)NSRC1 * D];   // 5.1 MB
__device__ float g_el0[NSRC0];
__device__ float g_el1[NSRC1];
__device__ float g_er0[NDST];
__device__ float g_er1[NDST];
__device__ float g_e0[(size_t)NDST * D];       // 51.2 MB
__device__ float g_e1[(size_t)NDST * D];       // 51.2 MB
__device__ float g_w0[D];                      // W_dst0 @ a_r0
__device__ float g_w1[D];                      // W_dst1 @ a_r1
__device__ float g_wt[D * D];                  // W_fc transposed
__device__ float g_sp0p[SPB * D];              // per-block partials (deterministic)
__device__ float g_sp1p[SPB * D];
__device__ float g_beta[2];

// ---------------- prep: er-vectors, W_fc transpose ----------------
__global__ void prep_kernel(const float* __restrict__ Wd0, const float* __restrict__ ar0,
                            const float* __restrict__ Wd1, const float* __restrict__ ar1,
                            const float* __restrict__ Wfc) {
    int t = threadIdx.x;  // 128 threads
    float s0 = 0.f, s1 = 0.f;
    for (int d = 0; d < D; d++) {
        s0 = fmaf(Wd0[t * D + d], ar0[d], s0);
        s1 = fmaf(Wd1[t * D + d], ar1[d], s1);
    }
    g_w0[t] = s0;
    g_w1[t] = s1;
    for (int d = 0; d < D; d++) g_wt[d * D + t] = Wfc[t * D + d];
}

// ---------------- feat GEMM: C = A[N,128] @ W[128,128], el = C @ a_l ----------------
// 128x128 tile per block, 256 threads, 8x8 register tile (packed f32x2), BK=32.
template <int REL>
__global__ __launch_bounds__(256, 2) void gemm_feat(const float* __restrict__ A,
                                                    const float* __restrict__ W,
                                                    const float* __restrict__ al, int N) {
    float* __restrict__ C  = REL ? g_feat1 : g_feat0;
    float* __restrict__ el = REL ? g_el1 : g_el0;
    __shared__ float As[128 * 32];
    __shared__ float Ws[32 * 128];

    const int tid = threadIdx.x;
    const int tx = tid & 15;     // 16 col-groups of 8 cols
    const int ty = tid >> 4;     // 16 row-groups of 8 rows
    const int c0 = tx * 8;
    const int r0 = ty * 8;
    const int rowBase = blockIdx.x * 128;

    u64 accp[8][4];
#pragma unroll
    for (int i = 0; i < 8; i++)
#pragma unroll
        for (int j = 0; j < 4; j++) accp[i][j] = 0ull;

    for (int kb = 0; kb < D; kb += 32) {
#pragma unroll
        for (int p = 0; p < 4; p++) {
            int lin = tid + p * 256;
            int r = lin >> 3, q = lin & 7;
            int grow = rowBase + r;
            float4 v = make_float4(0.f, 0.f, 0.f, 0.f);
            if (grow < N) v = *(const float4*)(A + (size_t)grow * D + kb + q * 4);
            *(float4*)(As + r * 32 + q * 4) = v;
        }
#pragma unroll
        for (int p = 0; p < 4; p++) {
            int lin = tid + p * 256;
            int kr = lin >> 5, q = lin & 31;
            *(float4*)(Ws + kr * 128 + q * 4) =
                *(const float4*)(W + (size_t)(kb + kr) * D + q * 4);
        }
        __syncthreads();
#pragma unroll 8
        for (int k = 0; k < 32; k++) {
            u64 apk[8];
#pragma unroll
            for (int i = 0; i < 8; i++) apk[i] = pack_dup(As[(r0 + i) * 32 + k]);
            const u64* bp = (const u64*)(Ws + k * 128 + c0);
            u64 bpk[4] = {bp[0], bp[1], bp[2], bp[3]};
#pragma unroll
            for (int i = 0; i < 8; i++)
#pragma unroll
                for (int j = 0; j < 4; j++) ffma2(accp[i][j], apk[i], bpk[j]);
        }
        __syncthreads();
    }

    float acc[8][8];
#pragma unroll
    for (int i = 0; i < 8; i++)
#pragma unroll
        for (int j = 0; j < 4; j++) unpack2(accp[i][j], acc[i][2 * j], acc[i][2 * j + 1]);

    // epilogue: store feat + fused el = feat @ a_l (16-lane shuffle reduce)
    float4 av0 = *(const float4*)(al + c0);
    float4 av1 = *(const float4*)(al + c0 + 4);
    float alv[8] = {av0.x, av0.y, av0.z, av0.w, av1.x, av1.y, av1.z, av1.w};
#pragma unroll
    for (int i = 0; i < 8; i++) {
        int grow = rowBase + r0 + i;
        if (grow < N) {
            *(float4*)(C + (size_t)grow * D + c0) =
                make_float4(acc[i][0], acc[i][1], acc[i][2], acc[i][3]);
            *(float4*)(C + (size_t)grow * D + c0 + 4) =
                make_float4(acc[i][4], acc[i][5], acc[i][6], acc[i][7]);
        }
        float p = 0.f;
#pragma unroll
        for (int j = 0; j < 8; j++) p = fmaf(acc[i][j], alv[j], p);
#pragma unroll
        for (int s = 8; s > 0; s >>= 1) p += __shfl_xor_sync(0xffffffffu, p, s, 16);
        if (tx == 0 && grow < N) el[grow] = p;
    }
}

// ---------------- er matvec: er{0,1}[n] = h_dst[n] . w{0,1} ----------------
__global__ void er_kernel(const float* __restrict__ hdst) {
    int gw = (int)(((size_t)blockIdx.x * blockDim.x + threadIdx.x) >> 5);
    int lane = threadIdx.x & 31;
    if (gw >= NDST) return;
    float4 h = *(const float4*)(hdst + (size_t)gw * D + lane * 4);
    float4 a = *(const float4*)(g_w0 + lane * 4);
    float4 b = *(const float4*)(g_w1 + lane * 4);
    float s0 = h.x * a.x + h.y * a.y + h.z * a.z + h.w * a.w;
    float s1 = h.x * b.x + h.y * b.y + h.z * b.z + h.w * b.w;
#pragma unroll
    for (int s = 16; s > 0; s >>= 1) {
        s0 += __shfl_xor_sync(0xffffffffu, s0, s);
        s1 += __shfl_xor_sync(0xffffffffu, s1, s);
    }
    if (lane == 0) {
        g_er0[gw] = s0;
        g_er1[gw] = s1;
    }
}

// ---------------- GAT aggregation: edge softmax + weighted gather ----------------
template <int REL>
__global__ void gat_agg(const int* __restrict__ idx, const float* __restrict__ bias) {
    constexpr int K = REL ? K1 : K0;
    const float* __restrict__ feat = REL ? g_feat1 : g_feat0;
    const float* __restrict__ el = REL ? g_el1 : g_el0;
    const float* __restrict__ er = REL ? g_er1 : g_er0;
    float* __restrict__ eout = REL ? g_e1 : g_e0;

    int n = blockIdx.x;
    __shared__ float e_s[K];
    __shared__ float alpha_s[K];
    __shared__ int idx_s[K];
    int t = threadIdx.x;  // 128

    if (t < K) {
        int i = idx[(size_t)n * K + t];
        float v = el[i] + er[n];
        e_s[t] = v > 0.f ? v : 0.2f * v;  // leaky_relu 0.2
        idx_s[t] = i;
    }
    __syncthreads();
    if (t == 0) {
        float m = e_s[0];
#pragma unroll
        for (int k = 1; k < K; k++) m = fmaxf(m, e_s[k]);
        float sum = 0.f;
        float p[K];
#pragma unroll
        for (int k = 0; k < K; k++) { p[k] = expf(e_s[k] - m); sum += p[k]; }
        float inv = 1.f / sum;
#pragma unroll
        for (int k = 0; k < K; k++) alpha_s[k] = p[k] * inv;
    }
    __syncthreads();
    float acc = bias[t];
#pragma unroll
    for (int k = 0; k < K; k++)
        acc = fmaf(alpha_s[k], feat[(size_t)idx_s[k] * D + t], acc);
    eout[(size_t)n * D + t] = acc;
}

// ---------------- sp reduce: partials of sum_n tanh(e_n @ W_fc^T + b_fc) ----------------
template <int REL>
__global__ __launch_bounds__(256, 2) void sp_gemm(const float* __restrict__ bfc) {
    const float* __restrict__ E = REL ? g_e1 : g_e0;
    float* __restrict__ part = REL ? g_sp1p : g_sp0p;
    const int N = NDST;
    __shared__ float As[128 * 32];
    __shared__ float Ws[32 * 128];
    __shared__ float red[16 * 128];

    const int tid = threadIdx.x;
    const int tx = tid & 15;
    const int ty = tid >> 4;
    const int c0 = tx * 8;
    const int r0 = ty * 8;
    const int rowBase = blockIdx.x * 128;

    u64 accp[8][4];
#pragma unroll
    for (int i = 0; i < 8; i++)
#pragma unroll
        for (int j = 0; j < 4; j++) accp[i][j] = 0ull;

    for (int kb = 0; kb < D; kb += 32) {
#pragma unroll
        for (int p = 0; p < 4; p++) {
            int lin = tid + p * 256;
            int r = lin >> 3, q = lin & 7;
            int grow = rowBase + r;
            float4 v = make_float4(0.f, 0.f, 0.f, 0.f);
            if (grow < N) v = *(const float4*)(E + (size_t)grow * D + kb + q * 4);
            *(float4*)(As + r * 32 + q * 4) = v;
        }
#pragma unroll
        for (int p = 0; p < 4; p++) {
            int lin = tid + p * 256;
            int kr = lin >> 5, q = lin & 31;
            *(float4*)(Ws + kr * 128 + q * 4) =
                *(const float4*)(g_wt + (size_t)(kb + kr) * D + q * 4);
        }
        __syncthreads();
#pragma unroll 8
        for (int k = 0; k < 32; k++) {
            u64 apk[8];
#pragma unroll
            for (int i = 0; i < 8; i++) apk[i] = pack_dup(As[(r0 + i) * 32 + k]);
            const u64* bp = (const u64*)(Ws + k * 128 + c0);
            u64 bpk[4] = {bp[0], bp[1], bp[2], bp[3]};
#pragma unroll
            for (int i = 0; i < 8; i++)
#pragma unroll
                for (int j = 0; j < 4; j++) ffma2(accp[i][j], apk[i], bpk[j]);
        }
        __syncthreads();
    }

    float acc[8][8];
#pragma unroll
    for (int i = 0; i < 8; i++)
#pragma unroll
        for (int j = 0; j < 4; j++) unpack2(accp[i][j], acc[i][2 * j], acc[i][2 * j + 1]);

    float4 b0v = *(const float4*)(bfc + c0);
    float4 b1v = *(const float4*)(bfc + c0 + 4);
    float bf[8] = {b0v.x, b0v.y, b0v.z, b0v.w, b1v.x, b1v.y, b1v.z, b1v.w};
    float s[8] = {0.f, 0.f, 0.f, 0.f, 0.f, 0.f, 0.f, 0.f};
#pragma unroll
    for (int i = 0; i < 8; i++) {
        int grow = rowBase + r0 + i;
        if (grow < N) {
#pragma unroll
            for (int j = 0; j < 8; j++) s[j] += tanhf(acc[i][j] + bf[j]);
        }
    }
#pragma unroll
    for (int j = 0; j < 8; j++) red[ty * 128 + c0 + j] = s[j];
    __syncthreads();
    if (tid < 128) {
        float t = 0.f;
#pragma unroll
        for (int y = 0; y < 16; y++) t += red[y * 128 + tid];
        part[blockIdx.x * 128 + tid] = t;  // deterministic: no atomics
    }
}

// ---------------- beta: softmax over relation scores ----------------
__global__ void beta_kernel(const float* __restrict__ att) {
    __shared__ float r[128];
    __shared__ float res0;
    int t = threadIdx.x;  // 128
    float s0 = 0.f, s1 = 0.f;
    for (int b = 0; b < SPB; b++) {
        s0 += g_sp0p[b * 128 + t];
        s1 += g_sp1p[b * 128 + t];
    }
    float a = att[t];
    r[t] = a * s0;
    __syncthreads();
    for (int off = 64; off > 0; off >>= 1) {
        if (t < off) r[t] += r[t + off];
        __syncthreads();
    }
    if (t == 0) res0 = r[0];
    __syncthreads();
    r[t] = a * s1;
    __syncthreads();
    for (int off = 64; off > 0; off >>= 1) {
        if (t < off) r[t] += r[t + off];
        __syncthreads();
    }
    if (t == 0) {
        float p0 = res0 / (float)NDST;
        float p1 = r[0] / (float)NDST;
        float m = fmaxf(p0, p1);
        float e0 = expf(p0 - m), e1 = expf(p1 - m);
        float inv = 1.f / (e0 + e1);
        g_beta[0] = e0 * inv;
        g_beta[1] = e1 * inv;
    }
}

// ---------------- final blend ----------------
__global__ void combine_kernel(float* __restrict__ out) {
    float b0 = g_beta[0], b1 = g_beta[1];
    size_t i = (size_t)blockIdx.x * blockDim.x + threadIdx.x;
    const size_t tot = (size_t)NDST * D / 4;
    if (i >= tot) return;
    float4 x = ((const float4*)g_e0)[i];
    float4 y = ((const float4*)g_e1)[i];
    float4 r;
    r.x = b0 * x.x + b1 * y.x;
    r.y = b0 * x.y + b1 * y.y;
    r.z = b0 * x.z + b1 * y.z;
    r.w = b0 * x.w + b1 * y.w;
    ((float4*)out)[i] = r;
}

// ---------------- launch ----------------
extern "C" void kernel_launch(void* const* d_in, const int* in_sizes, int n_in,
                              void* d_out, int out_size) {
    const float* h_src0 = (const float*)d_in[0];
    const float* h_src1 = (const float*)d_in[1];
    const float* h_dst  = (const float*)d_in[2];
    const int*   idx0   = (const int*)d_in[3];
    const int*   idx1   = (const int*)d_in[4];
    const float* W_src0 = (const float*)d_in[5];
    const float* W_dst0 = (const float*)d_in[6];
    const float* a_l0   = (const float*)d_in[7];
    const float* a_r0   = (const float*)d_in[8];
    const float* b0     = (const float*)d_in[9];
    const float* W_src1 = (const float*)d_in[10];
    const float* W_dst1 = (const float*)d_in[11];
    const float* a_l1   = (const float*)d_in[12];
    const float* a_r1   = (const float*)d_in[13];
    const float* b1     = (const float*)d_in[14];
    const float* W_fc   = (const float*)d_in[15];
    const float* b_fc   = (const float*)d_in[16];
    const float* att    = (const float*)d_in[17];
    float* out = (float*)d_out;

    prep_kernel<<<1, 128>>>(W_dst0, a_r0, W_dst1, a_r1, W_fc);
    gemm_feat<0><<<NSRC0 / 128, 256>>>(h_src0, W_src0, a_l0, NSRC0);
    gemm_feat<1><<<(NSRC1 + 127) / 128, 256>>>(h_src1, W_src1, a_l1, NSRC1);
    er_kernel<<<(NDST * 32 + 255) / 256, 256>>>(h_dst);
    gat_agg<0><<<NDST, 128>>>(idx0, b0);
    gat_agg<1><<<NDST, 128>>>(idx1, b1);
    sp_gemm<0><<<SPB, 256>>>(b_fc);
    sp_gemm<1><<<SPB, 256>>>(b_fc);
    beta_kernel<<<1, 128>>>(att);
    combine_kernel<<<(NDST * D / 4 + 255) / 256, 256>>>(out);
}